// round 6
// baseline (speedup 1.0000x reference)
#include <cuda_runtime.h>
#include <cuda_fp16.h>
#include <cstdint>

// Sinkhorn-Knopp, fp16 matrix. E is read from DRAM EXACTLY ONCE per iteration:
// persistent-per-iter CTAs stage 4-row groups (64KB) in SMEM via a 3-deep
// cp.async.cg pipeline; rowsums AND col partials are computed from SMEM.
// Col partials accumulate in registers across each CTA's ~14 groups.
//   E' = 1024*exp(-10*C) fp16 (normal range; global scale cancels)
//   iter: per group: eu_r = (d_r+eps)/sum_j E_rj evh_j ; colacc_j += eu_r E_rj
//   col_reduce: ev_j = (s_j+eps)/sum_{cta} part[cta][j] (fixed order)
//   P = eu_i E'_ij ev_j

#define NN 8192
#define NC4 (NN / 8)                 // 1024 uint4 chunks (8 halves) per row
#define GROWS 4                      // rows per group (64 KB)
#define NGROUPS (NN / GROWS)         // 2048
#define NCTAS 148
#define EPS 1e-6f
#define ESCALE 1024.0f

// smem layout (bytes)
#define SM_BUF   0                   // 3 * 4 * 1024 * 16 = 196608
#define SM_EVH   196608              // 1024 * 16       = 16384
#define SM_WPART 212992              // 4 * 32 * 4      = 512
#define SM_EUS   213504              // 4 * 4           = 16
#define SM_TOTAL 213520

__device__ __half g_E[(size_t)NN * NN];           // 128 MB
__device__ float  g_eu[NN];
__device__ float  g_ev[NN];                       // fp32 (final kernel)
__device__ __half g_evh[NN];                      // fp16 (hot loop)
__device__ float  g_part[(size_t)NCTAS * NN];     // 4.85 MB

__device__ __forceinline__ void cpa16(uint32_t smem_dst, const void* gsrc) {
    asm volatile("cp.async.cg.shared.global [%0], [%1], 16;\n"
                 :: "r"(smem_dst), "l"(gsrc));
}
#define CP_COMMIT() asm volatile("cp.async.commit_group;\n" ::: "memory")
#define CP_WAIT2()  asm volatile("cp.async.wait_group 2;\n" ::: "memory")

// FMA-only exp for x in [-15, 0]
__device__ __forceinline__ float fast_exp_neg(float x) {
    const float LOG2E = 1.4426950408889634f;
    float t = x * LOG2E;
    float n = rintf(t);
    float f = t - n;
    float p = 1.5403530393381608e-4f;
    p = fmaf(p, f, 1.3333558146428443e-3f);
    p = fmaf(p, f, 9.6181291076284770e-3f);
    p = fmaf(p, f, 5.5504108664821580e-2f);
    p = fmaf(p, f, 2.4022650695910070e-1f);
    p = fmaf(p, f, 6.9314718055994530e-1f);
    p = fmaf(p, f, 1.0f);
    return p * __int_as_float(((int)n + 127) << 23);
}

// ---------------------------------------------------------------------------
__global__ void precompute_kernel(const float* __restrict__ C) {
    size_t g = (size_t)blockIdx.x * blockDim.x + threadIdx.x;
    const float4* C4 = reinterpret_cast<const float4*>(C);
    float4 c0 = C4[2 * g];
    float4 c1 = C4[2 * g + 1];
    __half2 h[4];
    h[0] = __floats2half2_rn(ESCALE * fast_exp_neg(-10.0f * c0.x),
                             ESCALE * fast_exp_neg(-10.0f * c0.y));
    h[1] = __floats2half2_rn(ESCALE * fast_exp_neg(-10.0f * c0.z),
                             ESCALE * fast_exp_neg(-10.0f * c0.w));
    h[2] = __floats2half2_rn(ESCALE * fast_exp_neg(-10.0f * c1.x),
                             ESCALE * fast_exp_neg(-10.0f * c1.y));
    h[3] = __floats2half2_rn(ESCALE * fast_exp_neg(-10.0f * c1.z),
                             ESCALE * fast_exp_neg(-10.0f * c1.w));
    reinterpret_cast<uint4*>(g_E)[g] = *reinterpret_cast<uint4*>(h);
    if (g < NN) {
        const float E1 = 2.718281828459045f;      // exp(v0), v0 = 1
        g_ev[g]  = E1;
        g_evh[g] = __float2half_rn(E1);
    }
}

// ---------------------------------------------------------------------------
// Fused iteration kernel: grid = 148 CTAs x 1024 threads, 1 CTA/SM.
// CTA c processes groups {c, c+148, ...} of 4 rows each via a 3-buffer
// cp.async pipeline. Col partials accumulate in registers across groups.
// ---------------------------------------------------------------------------
__global__ void __launch_bounds__(1024, 1)
iter_kernel(const float* __restrict__ d) {
    extern __shared__ char smraw[];
    uint4* buf   = reinterpret_cast<uint4*>(smraw + SM_BUF);    // [3][4][1024]
    uint4* evs   = reinterpret_cast<uint4*>(smraw + SM_EVH);    // [1024]
    float* wpart = reinterpret_cast<float*>(smraw + SM_WPART);  // [4][32]
    float* eu_s  = reinterpret_cast<float*>(smraw + SM_EUS);    // [4]

    const int tid  = threadIdx.x;
    const int wid  = tid >> 5;
    const int lane = tid & 31;
    const int cta  = blockIdx.x;
    const int ng   = (NGROUPS - cta + NCTAS - 1) / NCTAS;       // 13 or 14

    // stage evh into smem (visible after first in-loop barrier)
    evs[tid] = reinterpret_cast<const uint4*>(g_evh)[tid];

    const uint4* Eg = reinterpret_cast<const uint4*>(g_E);

    // helper: issue loads for pipeline slot of group t
    auto prefetch = [&](int t) {
        int gid   = cta + t * NCTAS;
        int grow0 = gid * GROWS;
        uint32_t base = (uint32_t)__cvta_generic_to_shared(buf + (t % 3) * 4096);
#pragma unroll
        for (int r = 0; r < GROWS; ++r) {
            cpa16(base + (uint32_t)(r * 1024 + tid) * 16,
                  Eg + (size_t)(grow0 + r) * NC4 + tid);
        }
    };

    // prologue: 2 groups in flight (ng >= 13 always)
    prefetch(0); CP_COMMIT();
    prefetch(1); CP_COMMIT();

    float acc0 = 0.f, acc1 = 0.f, acc2 = 0.f, acc3 = 0.f;
    float acc4 = 0.f, acc5 = 0.f, acc6 = 0.f, acc7 = 0.f;

    for (int t = 0; t < ng; ++t) {
        if (t + 2 < ng) prefetch(t + 2);
        CP_COMMIT();                 // possibly-empty group keeps counts aligned
        CP_WAIT2();                  // group t complete
        __syncthreads();

        const uint4* B = buf + (t % 3) * 4096;
        const int grow0 = (cta + t * NCTAS) * GROWS;

        // --- rowsums: thread t owns chunk `tid` of every row in the group ---
        uint4 ev4 = evs[tid];
        const __half2* hv = reinterpret_cast<const __half2*>(&ev4);
        float2 v0 = __half22float2(hv[0]);
        float2 v1 = __half22float2(hv[1]);
        float2 v2 = __half22float2(hv[2]);
        float2 v3 = __half22float2(hv[3]);
        float rp[GROWS];
#pragma unroll
        for (int r = 0; r < GROWS; ++r) {
            uint4 e = B[r * 1024 + tid];
            const __half2* he = reinterpret_cast<const __half2*>(&e);
            float2 f0 = __half22float2(he[0]);
            float2 f1 = __half22float2(he[1]);
            float2 f2 = __half22float2(he[2]);
            float2 f3 = __half22float2(he[3]);
            float a = f0.x * v0.x;
            a = fmaf(f0.y, v0.y, a);
            a = fmaf(f1.x, v1.x, a); a = fmaf(f1.y, v1.y, a);
            a = fmaf(f2.x, v2.x, a); a = fmaf(f2.y, v2.y, a);
            a = fmaf(f3.x, v3.x, a); a = fmaf(f3.y, v3.y, a);
            rp[r] = a;
        }
#pragma unroll
        for (int o = 16; o > 0; o >>= 1) {
            rp[0] += __shfl_down_sync(0xFFFFFFFFu, rp[0], o);
            rp[1] += __shfl_down_sync(0xFFFFFFFFu, rp[1], o);
            rp[2] += __shfl_down_sync(0xFFFFFFFFu, rp[2], o);
            rp[3] += __shfl_down_sync(0xFFFFFFFFu, rp[3], o);
        }
        if (lane == 0) {
#pragma unroll
            for (int r = 0; r < GROWS; ++r)
                wpart[r * 32 + wid] = rp[r];
        }
        __syncthreads();
        if (tid < 128) {
            int r = tid >> 5, k = tid & 31;
            float v = wpart[r * 32 + k];
#pragma unroll
            for (int o = 16; o > 0; o >>= 1)
                v += __shfl_down_sync(0xFFFFFFFFu, v, o);
            if (k == 0) {
                float eu = (d[grow0 + r] + EPS) / v;
                eu_s[r] = eu;
                g_eu[grow0 + r] = eu;             // consumed by final_kernel
            }
        }
        __syncthreads();

        // --- col partials: accumulate into persistent registers -------------
        float u0 = eu_s[0], u1 = eu_s[1], u2 = eu_s[2], u3 = eu_s[3];
#pragma unroll
        for (int r = 0; r < GROWS; ++r) {
            float u = (r == 0) ? u0 : (r == 1) ? u1 : (r == 2) ? u2 : u3;
            uint4 e = B[r * 1024 + tid];
            const __half2* he = reinterpret_cast<const __half2*>(&e);
            float2 f0 = __half22float2(he[0]);
            float2 f1 = __half22float2(he[1]);
            float2 f2 = __half22float2(he[2]);
            float2 f3 = __half22float2(he[3]);
            acc0 = fmaf(f0.x, u, acc0); acc1 = fmaf(f0.y, u, acc1);
            acc2 = fmaf(f1.x, u, acc2); acc3 = fmaf(f1.y, u, acc3);
            acc4 = fmaf(f2.x, u, acc4); acc5 = fmaf(f2.y, u, acc5);
            acc6 = fmaf(f3.x, u, acc6); acc7 = fmaf(f3.y, u, acc7);
        }
        __syncthreads();             // buffer slot reusable by next prefetch
    }

    // write CTA column partials (thread owns cols 8*tid .. 8*tid+7)
    float4* P4 = reinterpret_cast<float4*>(g_part + (size_t)cta * NN);
    P4[2 * tid]     = make_float4(acc0, acc1, acc2, acc3);
    P4[2 * tid + 1] = make_float4(acc4, acc5, acc6, acc7);
}

// ---------------------------------------------------------------------------
// ev_j = (s_j+eps) / sum over 148 CTA partials (fixed order, deterministic).
// grid = 32 CTAs x 256 threads; thread (g, slice): col4 = blk*64+g,
// slice sums 37 CTAs (148 = 4*37), then fixed-order combine in smem.
// ---------------------------------------------------------------------------
__global__ void col_reduce_kernel(const float* __restrict__ s) {
    __shared__ float4 red[4][64];
    const int g     = threadIdx.x & 63;
    const int slice = threadIdx.x >> 6;          // 0..3
    const int col4  = blockIdx.x * 64 + g;       // 0..2047
    const float4* P4 = reinterpret_cast<const float4*>(g_part);
    float4 acc = make_float4(0.f, 0.f, 0.f, 0.f);
#pragma unroll
    for (int k = 0; k < 37; ++k) {
        float4 v = P4[(size_t)(slice * 37 + k) * (NN / 4) + col4];
        acc.x += v.x; acc.y += v.y; acc.z += v.z; acc.w += v.w;
    }
    red[slice][g] = acc;
    __syncthreads();
    if (slice == 0) {
        float4 t = red[0][g];
#pragma unroll
        for (int q = 1; q < 4; ++q) {            // fixed order
            float4 r = red[q][g];
            t.x += r.x; t.y += r.y; t.z += r.z; t.w += r.w;
        }
        int j0 = col4 * 4;
        float e0 = (s[j0 + 0] + EPS) / t.x;
        float e1 = (s[j0 + 1] + EPS) / t.y;
        float e2 = (s[j0 + 2] + EPS) / t.z;
        float e3 = (s[j0 + 3] + EPS) / t.w;
        reinterpret_cast<float4*>(g_ev)[col4] = make_float4(e0, e1, e2, e3);
        __half2* VH2 = reinterpret_cast<__half2*>(g_evh);
        VH2[2 * col4]     = __floats2half2_rn(e0, e1);
        VH2[2 * col4 + 1] = __floats2half2_rn(e2, e3);
    }
}

// ---------------------------------------------------------------------------
// Final: P_ij = eu_i * E'_ij * ev_j   (fp32 eu/ev)
// ---------------------------------------------------------------------------
__global__ void final_kernel(float* __restrict__ out) {
    size_t idx = (size_t)blockIdx.x * blockDim.x + threadIdx.x;
    int row = (int)(idx / NC4);
    int c8  = (int)(idx % NC4);
    float u = g_eu[row];
    const float4* ev4 = reinterpret_cast<const float4*>(g_ev);
    float4 v0 = ev4[2 * c8];
    float4 v1 = ev4[2 * c8 + 1];
    uint4 e = reinterpret_cast<const uint4*>(g_E)[idx];
    const __half2* hp = reinterpret_cast<const __half2*>(&e);
    float2 f0 = __half22float2(hp[0]);
    float2 f1 = __half22float2(hp[1]);
    float2 f2 = __half22float2(hp[2]);
    float2 f3 = __half22float2(hp[3]);
    float4 p0, p1;
    p0.x = u * f0.x * v0.x;  p0.y = u * f0.y * v0.y;
    p0.z = u * f1.x * v0.z;  p0.w = u * f1.y * v0.w;
    p1.x = u * f2.x * v1.x;  p1.y = u * f2.y * v1.y;
    p1.z = u * f3.x * v1.z;  p1.w = u * f3.y * v1.w;
    float4* O4 = reinterpret_cast<float4*>(out);
    O4[2 * idx]     = p0;
    O4[2 * idx + 1] = p1;
}

// ---------------------------------------------------------------------------
extern "C" void kernel_launch(void* const* d_in, const int* in_sizes, int n_in,
                              void* d_out, int out_size) {
    const float* C = (const float*)d_in[0];
    const float* d = (const float*)d_in[1];
    const float* s = (const float*)d_in[2];
    float* out = (float*)d_out;

    // immediate (non-stream) API; idempotent; no allocation
    cudaFuncSetAttribute(iter_kernel,
                         cudaFuncAttributeMaxDynamicSharedMemorySize, SM_TOTAL);

    const int VBLOCKS = (NN * NC4) / 256;    // 32768

    precompute_kernel<<<VBLOCKS, 256>>>(C);

    for (int it = 0; it < 50; ++it) {
        iter_kernel<<<NCTAS, 1024, SM_TOTAL>>>(d);
        col_reduce_kernel<<<32, 256>>>(s);
    }

    final_kernel<<<VBLOCKS, 256>>>(out);
}

// round 7
// speedup vs baseline: 1.1419x; 1.1419x over previous
#include <cuda_runtime.h>
#include <cuda_fp16.h>
#include <cstdint>

// Sinkhorn-Knopp, fp16 matrix. ONE DRAM sweep per iteration via cp.async SMEM
// staging (R6) + 2 CTAs/SM latency overlap (R5) + thread-private buffer
// ownership (no buffer barriers: each thread copies exactly the chunks it
// reads). 2 barriers per 2-row group (row-partial publish, eu publish).
//   E' = 1024*exp(-10*C) fp16; global scale cancels exactly.
//   iter: per group: eu_r = (d_r+eps)/sum_j E_rj evh_j ; colacc_j += eu_r E_rj
//   col_reduce: ev_j = (s_j+eps)/sum_{cta} part[cta][j] (fixed order)
//   P = eu_i E'_ij ev_j

#define NN 8192
#define NC4 (NN / 8)                 // 1024 uint4 chunks (8 halves) per row
#define GROWS 2                      // rows per group (32 KB)
#define NGROUPS (NN / GROWS)         // 4096
#define NCTAS 296                    // 2 CTAs per SM
#define NTHR 512
#define EPS 1e-6f
#define ESCALE 1024.0f

// smem layout (bytes): 3 buffers x 2 rows x 1024 uint4 = 98304
#define SM_BUF   0
#define SM_WPART 98304               // float[2][16]
#define SM_EUS   98432               // float[2]
#define SM_TOTAL 98560

__device__ __align__(16) __half g_E[(size_t)NN * NN];        // 128 MB
__device__ __align__(16) float  g_eu[NN];
__device__ __align__(16) float  g_ev[NN];                    // fp32 (final)
__device__ __align__(16) __half g_evh[NN];                   // fp16 (hot loop)
__device__ __align__(16) float  g_part[(size_t)NCTAS * NN];  // 9.7 MB

__device__ __forceinline__ void cpa16(uint32_t smem_dst, const void* gsrc) {
    asm volatile("cp.async.cg.shared.global [%0], [%1], 16;\n"
                 :: "r"(smem_dst), "l"(gsrc));
}
#define CP_COMMIT() asm volatile("cp.async.commit_group;\n" ::: "memory")
#define CP_WAIT2()  asm volatile("cp.async.wait_group 2;\n" ::: "memory")

// FMA-only exp for x in [-15, 0]
__device__ __forceinline__ float fast_exp_neg(float x) {
    const float LOG2E = 1.4426950408889634f;
    float t = x * LOG2E;
    float n = rintf(t);
    float f = t - n;
    float p = 1.5403530393381608e-4f;
    p = fmaf(p, f, 1.3333558146428443e-3f);
    p = fmaf(p, f, 9.6181291076284770e-3f);
    p = fmaf(p, f, 5.5504108664821580e-2f);
    p = fmaf(p, f, 2.4022650695910070e-1f);
    p = fmaf(p, f, 6.9314718055994530e-1f);
    p = fmaf(p, f, 1.0f);
    return p * __int_as_float(((int)n + 127) << 23);
}

// ---------------------------------------------------------------------------
__global__ void precompute_kernel(const float* __restrict__ C) {
    size_t g = (size_t)blockIdx.x * blockDim.x + threadIdx.x;
    const float4* C4 = reinterpret_cast<const float4*>(C);
    float4 c0 = C4[2 * g];
    float4 c1 = C4[2 * g + 1];
    __half2 h[4];
    h[0] = __floats2half2_rn(ESCALE * fast_exp_neg(-10.0f * c0.x),
                             ESCALE * fast_exp_neg(-10.0f * c0.y));
    h[1] = __floats2half2_rn(ESCALE * fast_exp_neg(-10.0f * c0.z),
                             ESCALE * fast_exp_neg(-10.0f * c0.w));
    h[2] = __floats2half2_rn(ESCALE * fast_exp_neg(-10.0f * c1.x),
                             ESCALE * fast_exp_neg(-10.0f * c1.y));
    h[3] = __floats2half2_rn(ESCALE * fast_exp_neg(-10.0f * c1.z),
                             ESCALE * fast_exp_neg(-10.0f * c1.w));
    reinterpret_cast<uint4*>(g_E)[g] = *reinterpret_cast<uint4*>(h);
    if (g < NN) {
        const float E1 = 2.718281828459045f;      // exp(v0), v0 = 1
        g_ev[g]  = E1;
        g_evh[g] = __float2half_rn(E1);
    }
}

// ---------------------------------------------------------------------------
// Fused iteration kernel: 296 CTAs x 512 threads, 2 CTAs/SM.
// CTA c handles 2-row groups {c, c+296, ...}. Thread t owns chunks t and
// t+512 of every row it touches (copies them, reads them -> no buf barriers).
// ---------------------------------------------------------------------------
__global__ void __launch_bounds__(NTHR, 2)
iter_kernel(const float* __restrict__ d) {
    extern __shared__ char smraw[];
    uint4* buf   = reinterpret_cast<uint4*>(smraw + SM_BUF);   // [3][2][1024]
    float* wpart = reinterpret_cast<float*>(smraw + SM_WPART); // [2][16]
    float* eu_s  = reinterpret_cast<float*>(smraw + SM_EUS);   // [2]

    const int tid  = threadIdx.x;
    const int wid  = tid >> 5;
    const int lane = tid & 31;
    const int cta  = blockIdx.x;
    const int ng   = (NGROUPS - cta + NCTAS - 1) / NCTAS;      // 13 or 14

    const uint4* Eg  = reinterpret_cast<const uint4*>(g_E);
    const uint4* EVH = reinterpret_cast<const uint4*>(g_evh);

    const uint32_t smbase = (uint32_t)__cvta_generic_to_shared(buf);

    auto prefetch = [&](int t) {
        const int grow0 = (cta + t * NCTAS) * GROWS;
        const uint32_t sb = smbase + (uint32_t)((t % 3) * 2048) * 16u;
#pragma unroll
        for (int r = 0; r < GROWS; ++r) {
            const uint4* src = Eg + (size_t)(grow0 + r) * NC4;
            cpa16(sb + (uint32_t)(r * 1024 + tid) * 16u,       src + tid);
            cpa16(sb + (uint32_t)(r * 1024 + tid + 512) * 16u, src + tid + 512);
        }
    };

    prefetch(0); CP_COMMIT();
    prefetch(1); CP_COMMIT();

    float ca[8] = {0.f, 0.f, 0.f, 0.f, 0.f, 0.f, 0.f, 0.f};   // cols of chunk tid
    float cb[8] = {0.f, 0.f, 0.f, 0.f, 0.f, 0.f, 0.f, 0.f};   // cols of chunk tid+512

    for (int t = 0; t < ng; ++t) {
        if (t + 2 < ng) prefetch(t + 2);
        CP_COMMIT();
        CP_WAIT2();                   // own copies of group t complete

        const uint4* B = buf + (t % 3) * 2048;
        const int grow0 = (cta + t * NCTAS) * GROWS;

        // ---- phase 1: row partials (each thread: 2 chunks x 2 rows) -------
        float rp0 = 0.f, rp1 = 0.f;
        float va[8], vb[8];
        {
            uint4 ev = __ldg(EVH + tid);
            const __half2* hv = reinterpret_cast<const __half2*>(&ev);
#pragma unroll
            for (int k = 0; k < 4; ++k) {
                float2 v = __half22float2(hv[k]);
                va[2 * k] = v.x; va[2 * k + 1] = v.y;
            }
            ev = __ldg(EVH + tid + 512);
            hv = reinterpret_cast<const __half2*>(&ev);
#pragma unroll
            for (int k = 0; k < 4; ++k) {
                float2 v = __half22float2(hv[k]);
                vb[2 * k] = v.x; vb[2 * k + 1] = v.y;
            }
        }
#pragma unroll
        for (int r = 0; r < GROWS; ++r) {
            uint4 eA = B[r * 1024 + tid];
            uint4 eB = B[r * 1024 + tid + 512];
            const __half2* ha = reinterpret_cast<const __half2*>(&eA);
            const __half2* hb = reinterpret_cast<const __half2*>(&eB);
            float acc = 0.f;
#pragma unroll
            for (int k = 0; k < 4; ++k) {
                float2 fa = __half22float2(ha[k]);
                float2 fb = __half22float2(hb[k]);
                acc = fmaf(fa.x, va[2 * k], acc);
                acc = fmaf(fa.y, va[2 * k + 1], acc);
                acc = fmaf(fb.x, vb[2 * k], acc);
                acc = fmaf(fb.y, vb[2 * k + 1], acc);
            }
            if (r == 0) rp0 = acc; else rp1 = acc;
        }
#pragma unroll
        for (int o = 16; o > 0; o >>= 1) {
            rp0 += __shfl_down_sync(0xFFFFFFFFu, rp0, o);
            rp1 += __shfl_down_sync(0xFFFFFFFFu, rp1, o);
        }
        if (lane == 0) {
            wpart[wid]      = rp0;
            wpart[16 + wid] = rp1;
        }
        __syncthreads();

        if (wid == 0) {               // warp 0: two 16-wide reductions
            float x = wpart[lane];    // lanes 0-15: row0, 16-31: row1
#pragma unroll
            for (int o = 8; o > 0; o >>= 1)
                x += __shfl_down_sync(0xFFFFFFFFu, x, o, 16);
            if ((lane & 15) == 0) {
                int r = lane >> 4;
                float eu = (d[grow0 + r] + EPS) / x;
                eu_s[r] = eu;
                g_eu[grow0 + r] = eu;
            }
        }
        __syncthreads();

        // ---- phase 2: column accumulation (registers, persistent) ---------
        float u0 = eu_s[0], u1 = eu_s[1];
#pragma unroll
        for (int r = 0; r < GROWS; ++r) {
            float u = (r == 0) ? u0 : u1;
            uint4 eA = B[r * 1024 + tid];
            uint4 eB = B[r * 1024 + tid + 512];
            const __half2* ha = reinterpret_cast<const __half2*>(&eA);
            const __half2* hb = reinterpret_cast<const __half2*>(&eB);
#pragma unroll
            for (int k = 0; k < 4; ++k) {
                float2 fa = __half22float2(ha[k]);
                float2 fb = __half22float2(hb[k]);
                ca[2 * k]     = fmaf(fa.x, u, ca[2 * k]);
                ca[2 * k + 1] = fmaf(fa.y, u, ca[2 * k + 1]);
                cb[2 * k]     = fmaf(fb.x, u, cb[2 * k]);
                cb[2 * k + 1] = fmaf(fb.y, u, cb[2 * k + 1]);
            }
        }
        // no trailing barrier: thread-private buffer chunks
    }

    // write CTA column partials: chunk tid -> cols 8*tid.., chunk tid+512
    float4* P4 = reinterpret_cast<float4*>(g_part + (size_t)cta * NN);
    P4[2 * tid]             = make_float4(ca[0], ca[1], ca[2], ca[3]);
    P4[2 * tid + 1]         = make_float4(ca[4], ca[5], ca[6], ca[7]);
    P4[2 * (tid + 512)]     = make_float4(cb[0], cb[1], cb[2], cb[3]);
    P4[2 * (tid + 512) + 1] = make_float4(cb[4], cb[5], cb[6], cb[7]);
}

// ---------------------------------------------------------------------------
// ev_j = (s_j+eps) / sum over 296 CTA partials (fixed order, deterministic).
// grid = 64 CTAs x 256 threads; 8 slices x 37 partials; fixed-order combine.
// ---------------------------------------------------------------------------
__global__ void col_reduce_kernel(const float* __restrict__ s) {
    __shared__ float4 red[8][32];
    const int g     = threadIdx.x & 31;
    const int slice = threadIdx.x >> 5;          // 0..7
    const int col4  = blockIdx.x * 32 + g;       // 0..2047
    const float4* P4 = reinterpret_cast<const float4*>(g_part);
    float4 acc = make_float4(0.f, 0.f, 0.f, 0.f);
#pragma unroll
    for (int k = 0; k < 37; ++k) {
        float4 v = P4[(size_t)(slice * 37 + k) * (NN / 4) + col4];
        acc.x += v.x; acc.y += v.y; acc.z += v.z; acc.w += v.w;
    }
    red[slice][g] = acc;
    __syncthreads();
    if (slice == 0) {
        float4 t = red[0][g];
#pragma unroll
        for (int q = 1; q < 8; ++q) {            // fixed order
            float4 r = red[q][g];
            t.x += r.x; t.y += r.y; t.z += r.z; t.w += r.w;
        }
        int j0 = col4 * 4;
        float e0 = (s[j0 + 0] + EPS) / t.x;
        float e1 = (s[j0 + 1] + EPS) / t.y;
        float e2 = (s[j0 + 2] + EPS) / t.z;
        float e3 = (s[j0 + 3] + EPS) / t.w;
        reinterpret_cast<float4*>(g_ev)[col4] = make_float4(e0, e1, e2, e3);
        __half2* VH2 = reinterpret_cast<__half2*>(g_evh);
        VH2[2 * col4]     = __floats2half2_rn(e0, e1);
        VH2[2 * col4 + 1] = __floats2half2_rn(e2, e3);
    }
}

// ---------------------------------------------------------------------------
// Final: P_ij = eu_i * E'_ij * ev_j   (fp32 eu/ev)
// ---------------------------------------------------------------------------
__global__ void final_kernel(float* __restrict__ out) {
    size_t idx = (size_t)blockIdx.x * blockDim.x + threadIdx.x;
    int row = (int)(idx / NC4);
    int c8  = (int)(idx % NC4);
    float u = g_eu[row];
    const float4* ev4 = reinterpret_cast<const float4*>(g_ev);
    float4 v0 = ev4[2 * c8];
    float4 v1 = ev4[2 * c8 + 1];
    uint4 e = reinterpret_cast<const uint4*>(g_E)[idx];
    const __half2* hp = reinterpret_cast<const __half2*>(&e);
    float2 f0 = __half22float2(hp[0]);
    float2 f1 = __half22float2(hp[1]);
    float2 f2 = __half22float2(hp[2]);
    float2 f3 = __half22float2(hp[3]);
    float4 p0, p1;
    p0.x = u * f0.x * v0.x;  p0.y = u * f0.y * v0.y;
    p0.z = u * f1.x * v0.z;  p0.w = u * f1.y * v0.w;
    p1.x = u * f2.x * v1.x;  p1.y = u * f2.y * v1.y;
    p1.z = u * f3.x * v1.z;  p1.w = u * f3.y * v1.w;
    float4* O4 = reinterpret_cast<float4*>(out);
    O4[2 * idx]     = p0;
    O4[2 * idx + 1] = p1;
}

// ---------------------------------------------------------------------------
extern "C" void kernel_launch(void* const* d_in, const int* in_sizes, int n_in,
                              void* d_out, int out_size) {
    const float* C = (const float*)d_in[0];
    const float* d = (const float*)d_in[1];
    const float* s = (const float*)d_in[2];
    float* out = (float*)d_out;

    cudaFuncSetAttribute(iter_kernel,
                         cudaFuncAttributeMaxDynamicSharedMemorySize, SM_TOTAL);

    const int VBLOCKS = (NN * NC4) / 256;    // 32768

    precompute_kernel<<<VBLOCKS, 256>>>(C);

    for (int it = 0; it < 50; ++it) {
        iter_kernel<<<NCTAS, NTHR, SM_TOTAL>>>(d);
        col_reduce_kernel<<<64, 256>>>(s);
    }

    final_kernel<<<VBLOCKS, 256>>>(out);
}